// round 2
// baseline (speedup 1.0000x reference)
#include <cuda_runtime.h>
#include <math.h>
#include <stdint.h>

// ---------------- static config ----------------
#define TOK   100352          // 32 * 56 * 56 tokens
#define CDIM  256
#define NWIN  2048            // 32 * 64 windows
#define NTOK  49              // tokens per window
#define SCALE 0.17677669529663687f   // 32^-0.5

// ---------------- scratch (device globals; no allocs allowed) ----------------
__device__ float g_a[TOK * 256];      // LN1-window output; reused for attention output
__device__ float g_qkv[TOK * 768];    // QKV; first TOK*256 reused for LN2 output
__device__ float g_h[TOK * 1024];     // FC1/GELU output

// ---------------- LayerNorm (optionally fused with shift+window gather) ----------------
// WIN = true : read x at shifted/rolled source position, write window-layout row gw
// WIN = false: read row gw, write row gw
template<bool WIN>
__global__ void ln_kernel(const float* __restrict__ in, const float* __restrict__ gm,
                          const float* __restrict__ bt, float* __restrict__ out)
{
    int gw   = (blockIdx.x * blockDim.x + threadIdx.x) >> 5;
    int lane = threadIdx.x & 31;
    if (gw >= TOK) return;

    const float* src;
    if (WIN) {
        int ntok = gw % 49; int wb = gw / 49;
        int wwi = wb & 7, wh = (wb >> 3) & 7, b = wb >> 6;
        int r = ntok / 7, c = ntok % 7;
        int oh = wh * 7 + r + 3; if (oh >= 56) oh -= 56;
        int ow = wwi * 7 + c + 3; if (ow >= 56) ow -= 56;
        src = in + (size_t)(b * 3136 + oh * 56 + ow) * 256;
    } else {
        src = in + (size_t)gw * 256;
    }

    float v[8];
#pragma unroll
    for (int i = 0; i < 8; i++) v[i] = src[lane + 32 * i];

    float s = 0.f;
#pragma unroll
    for (int i = 0; i < 8; i++) s += v[i];
#pragma unroll
    for (int o = 16; o > 0; o >>= 1) s += __shfl_xor_sync(0xffffffffu, s, o);
    float mean = s * (1.0f / 256.0f);

    float q = 0.f;
#pragma unroll
    for (int i = 0; i < 8; i++) { float d = v[i] - mean; q += d * d; }
#pragma unroll
    for (int o = 16; o > 0; o >>= 1) q += __shfl_xor_sync(0xffffffffu, q, o);
    float rstd = rsqrtf(q * (1.0f / 256.0f) + 1e-5f);

    float* orow = out + (size_t)gw * 256;
#pragma unroll
    for (int i = 0; i < 8; i++) {
        int cc = lane + 32 * i;
        orow[cc] = (v[i] - mean) * rstd * gm[cc] + bt[cc];
    }
}

// ---------------- GEMM: C[M,NN] = A[M,K] @ B[K,NN] + epilogue ----------------
// MODE 0: out = acc + bias                                  (QKV)
// MODE 1: out[dst] = res[dst] + acc + bias, dst = unshift   (proj + scatter + residual)
// MODE 2: out = gelu(acc + bias)                            (FC1)
// MODE 3: out = res + acc + bias                            (FC2 + residual)
__device__ __forceinline__ float gelu_exact(float x)
{
    return 0.5f * x * (1.0f + erff(x * 0.70710678118654752f));
}

template<int K, int NN, int MODE>
__global__ __launch_bounds__(256) void sgemm_kernel(
    const float* __restrict__ A, const float* __restrict__ Bm,
    const float* __restrict__ bias, float* out, const float* res)
{
    __shared__ float As[2][8][132];   // [buf][k][m], padded to kill store conflicts
    __shared__ float Bs[2][8][128];   // [buf][k][n]

    const int bm = blockIdx.y, bn = blockIdx.x;
    const int tid = threadIdx.x;
    const int arow = tid >> 1;            // 0..127
    const int acol = (tid & 1) * 4;       // 0 or 4
    const int brow = tid >> 5;            // 0..7
    const int bcol = (tid & 31) * 4;      // 0..124
    const int tx = tid & 15;
    const int ty = tid >> 4;

    const float* Ap = A + (size_t)(bm * 128 + arow) * K + acol;
    const float* Bp = Bm + (size_t)brow * NN + bn * 128 + bcol;

    float acc[8][8];
#pragma unroll
    for (int i = 0; i < 8; i++)
#pragma unroll
        for (int j = 0; j < 8; j++) acc[i][j] = 0.f;

    float4 a4 = *(const float4*)Ap;
    float4 b4 = *(const float4*)Bp;
    As[0][acol + 0][arow] = a4.x; As[0][acol + 1][arow] = a4.y;
    As[0][acol + 2][arow] = a4.z; As[0][acol + 3][arow] = a4.w;
    *(float4*)&Bs[0][brow][bcol] = b4;
    __syncthreads();

    int buf = 0;
    const int KT = K / 8;
    for (int kt = 0; kt < KT; kt++) {
        const bool more = (kt + 1 < KT);
        if (more) {
            a4 = *(const float4*)(Ap + 8);
            b4 = *(const float4*)(Bp + (size_t)8 * NN);
            Ap += 8; Bp += (size_t)8 * NN;
        }
#pragma unroll
        for (int k = 0; k < 8; k++) {
            float4 x0 = *(const float4*)&As[buf][k][ty * 4];
            float4 x1 = *(const float4*)&As[buf][k][64 + ty * 4];
            float4 y0 = *(const float4*)&Bs[buf][k][tx * 4];
            float4 y1 = *(const float4*)&Bs[buf][k][64 + tx * 4];
            float ar[8] = {x0.x, x0.y, x0.z, x0.w, x1.x, x1.y, x1.z, x1.w};
            float br[8] = {y0.x, y0.y, y0.z, y0.w, y1.x, y1.y, y1.z, y1.w};
#pragma unroll
            for (int i = 0; i < 8; i++)
#pragma unroll
                for (int j = 0; j < 8; j++)
                    acc[i][j] += ar[i] * br[j];
        }
        if (more) {
            buf ^= 1;
            As[buf][acol + 0][arow] = a4.x; As[buf][acol + 1][arow] = a4.y;
            As[buf][acol + 2][arow] = a4.z; As[buf][acol + 3][arow] = a4.w;
            *(float4*)&Bs[buf][brow][bcol] = b4;
            __syncthreads();
        }
    }

    // ---- epilogue ----
#pragma unroll
    for (int i = 0; i < 8; i++) {
        int mr = bm * 128 + ((i < 4) ? (ty * 4 + i) : (64 + ty * 4 + (i - 4)));
        size_t dstrow;
        if (MODE == 1) {
            int ntok = mr % 49; int wb = mr / 49;
            int wwi = wb & 7, wh = (wb >> 3) & 7, b = wb >> 6;
            int r = ntok / 7, c = ntok % 7;
            int oh = wh * 7 + r + 3; if (oh >= 56) oh -= 56;
            int ow = wwi * 7 + c + 3; if (ow >= 56) ow -= 56;
            dstrow = (size_t)(b * 3136 + oh * 56 + ow);
        } else {
            dstrow = (size_t)mr;
        }
#pragma unroll
        for (int jg = 0; jg < 2; jg++) {
            int nc = bn * 128 + jg * 64 + tx * 4;
            float4 bb = *(const float4*)&bias[nc];
            float4 o;
            o.x = acc[i][jg * 4 + 0] + bb.x;
            o.y = acc[i][jg * 4 + 1] + bb.y;
            o.z = acc[i][jg * 4 + 2] + bb.z;
            o.w = acc[i][jg * 4 + 3] + bb.w;
            if (MODE == 1 || MODE == 3) {
                float4 rv = *(const float4*)&res[dstrow * NN + nc];
                o.x += rv.x; o.y += rv.y; o.z += rv.z; o.w += rv.w;
            }
            if (MODE == 2) {
                o.x = gelu_exact(o.x); o.y = gelu_exact(o.y);
                o.z = gelu_exact(o.z); o.w = gelu_exact(o.w);
            }
            *(float4*)&out[dstrow * NN + nc] = o;
        }
    }
}

// ---------------- windowed attention (one block per window-head) ----------------
__global__ __launch_bounds__(256) void attn_kernel(const float* __restrict__ qkv,
                                                   const float* __restrict__ rpb,
                                                   float* __restrict__ out)
{
    const int wb = blockIdx.x;   // 0..2047
    const int h  = blockIdx.y;   // 0..7
    const int tid = threadIdx.x;

    __shared__ float qs[49 * 33];
    __shared__ float ks[49 * 33];
    __shared__ float vs[49 * 33];
    __shared__ float sc[49 * 49];
    __shared__ float rpb_s[169];
    __shared__ int   lab[49];

    // load q (pre-scaled), k, v
    for (int idx = tid; idx < 49 * 32; idx += 256) {
        int n = idx >> 5, d = idx & 31;
        size_t base = (size_t)(wb * 49 + n) * 768 + h * 32 + d;
        qs[n * 33 + d] = qkv[base] * SCALE;
        ks[n * 33 + d] = qkv[base + 256];
        vs[n * 33 + d] = qkv[base + 512];
    }
    // relative position bias table slice for this head
    for (int i = tid; i < 169; i += 256) rpb_s[i] = rpb[i * 8 + h];
    // shift-mask region labels for this window
    if (tid < 49) {
        int wwi = wb & 7, wh = (wb >> 3) & 7;
        int r = tid / 7, c = tid % 7;
        int gr = wh * 7 + r, gc = wwi * 7 + c;
        int lr = gr < 49 ? 0 : (gr < 53 ? 1 : 2);
        int lc = gc < 49 ? 0 : (gc < 53 ? 1 : 2);
        lab[tid] = lr * 3 + lc;
    }
    __syncthreads();

    // scores = qk^T + bias + mask
    for (int idx = tid; idx < 49 * 49; idx += 256) {
        int i = idx / 49, j = idx % 49;
        float s = 0.f;
#pragma unroll
        for (int d = 0; d < 32; d++) s += qs[i * 33 + d] * ks[j * 33 + d];
        int ri = i / 7, ci = i % 7, rj = j / 7, cj = j % 7;
        s += rpb_s[(ri - rj + 6) * 13 + (ci - cj + 6)];
        if (lab[i] != lab[j]) s -= 100.0f;
        sc[idx] = s;
    }
    __syncthreads();

    // softmax per row
    if (tid < 49) {
        float mx = -1e30f;
#pragma unroll 7
        for (int j = 0; j < 49; j++) mx = fmaxf(mx, sc[tid * 49 + j]);
        float sum = 0.f;
#pragma unroll 7
        for (int j = 0; j < 49; j++) {
            float e = __expf(sc[tid * 49 + j] - mx);
            sc[tid * 49 + j] = e;
            sum += e;
        }
        float inv = 1.0f / sum;
#pragma unroll 7
        for (int j = 0; j < 49; j++) sc[tid * 49 + j] *= inv;
    }
    __syncthreads();

    // O = P @ V
    for (int idx = tid; idx < 49 * 32; idx += 256) {
        int i = idx >> 5, d = idx & 31;
        float o = 0.f;
#pragma unroll 7
        for (int j = 0; j < 49; j++) o += sc[i * 49 + j] * vs[j * 33 + d];
        out[(size_t)(wb * 49 + i) * 256 + h * 32 + d] = o;
    }
}

// ---------------- launch ----------------
extern "C" void kernel_launch(void* const* d_in, const int* in_sizes, int n_in,
                              void* d_out, int out_size)
{
    const float* x      = (const float*)d_in[0];
    const float* gamma1 = (const float*)d_in[1];
    const float* beta1  = (const float*)d_in[2];
    const float* qkv_w  = (const float*)d_in[3];
    const float* qkv_b  = (const float*)d_in[4];
    const float* proj_w = (const float*)d_in[5];
    const float* proj_b = (const float*)d_in[6];
    const float* rpb    = (const float*)d_in[7];
    const float* gamma2 = (const float*)d_in[8];
    const float* beta2  = (const float*)d_in[9];
    const float* fc1_w  = (const float*)d_in[10];
    const float* fc1_b  = (const float*)d_in[11];
    const float* fc2_w  = (const float*)d_in[12];
    const float* fc2_b  = (const float*)d_in[13];
    float* out = (float*)d_out;

    float *pa, *pqkv, *ph;
    cudaGetSymbolAddress((void**)&pa, g_a);
    cudaGetSymbolAddress((void**)&pqkv, g_qkv);
    cudaGetSymbolAddress((void**)&ph, g_h);

    // 1. LN1 + cyclic shift + window partition -> g_a [TOK, 256]
    ln_kernel<true><<<TOK / 8, 256>>>(x, gamma1, beta1, pa);
    // 2. QKV GEMM -> g_qkv [TOK, 768]
    sgemm_kernel<256, 768, 0><<<dim3(6, 784), 256>>>(pa, qkv_w, qkv_b, pqkv, nullptr);
    // 3. attention -> g_a (reused) [TOK, 256]
    attn_kernel<<<dim3(2048, 8), 256>>>(pqkv, rpb, pa);
    // 4. proj GEMM + window reverse + unroll-shift scatter + residual -> d_out (= x1)
    sgemm_kernel<256, 256, 1><<<dim3(2, 784), 256>>>(pa, proj_w, proj_b, out, x);
    // 5. LN2 -> g_qkv (reused as [TOK, 256])
    ln_kernel<false><<<TOK / 8, 256>>>(out, gamma2, beta2, pqkv);
    // 6. FC1 + GELU -> g_h [TOK, 1024]
    sgemm_kernel<256, 1024, 2><<<dim3(8, 784), 256>>>(pqkv, fc1_w, fc1_b, ph, nullptr);
    // 7. FC2 + residual -> d_out
    sgemm_kernel<1024, 256, 3><<<dim3(2, 784), 256>>>(ph, fc2_w, fc2_b, out, out);
    (void)in_sizes; (void)n_in; (void)out_size;
}

// round 3
// speedup vs baseline: 1.8175x; 1.8175x over previous
#include <cuda_runtime.h>
#include <math.h>
#include <stdint.h>

// ---------------- static config ----------------
#define TOK   100352          // 32 * 56 * 56 tokens
#define CDIM  256
#define NWIN  2048            // 32 * 64 windows
#define NTOK  49              // tokens per window
#define SCALE 0.17677669529663687f   // 32^-0.5

// ---------------- scratch (device globals; no allocs allowed) ----------------
__device__ float g_a[TOK * 256];      // LN1-window output; reused for attention output
__device__ float g_qkv[TOK * 768];    // QKV; first TOK*256 reused for LN2 output
__device__ float g_h[TOK * 1024];     // FC1/GELU output

// ---------------- helpers ----------------
__device__ __forceinline__ uint32_t f2tf32(float f)
{
    uint32_t u;
    asm("cvt.rna.tf32.f32 %0, %1;" : "=r"(u) : "f"(f));
    return u;
}

__device__ __forceinline__ float gelu_exact(float x)
{
    return 0.5f * x * (1.0f + erff(x * 0.70710678118654752f));
}

// unshifted destination row for window-layout row mr (window reverse + roll)
__device__ __forceinline__ int unshift_row(int mr)
{
    int ntok = mr % 49; int wb = mr / 49;
    int wwi = wb & 7, wh = (wb >> 3) & 7, b = wb >> 6;
    int r = ntok / 7, c = ntok % 7;
    int oh = wh * 7 + r + 3; if (oh >= 56) oh -= 56;
    int ow = wwi * 7 + c + 3; if (ow >= 56) ow -= 56;
    return b * 3136 + oh * 56 + ow;
}

// ---------------- LayerNorm (optionally fused with shift+window gather) ----------------
template<bool WIN>
__global__ void ln_kernel(const float* __restrict__ in, const float* __restrict__ gm,
                          const float* __restrict__ bt, float* __restrict__ out)
{
    int gw   = (blockIdx.x * blockDim.x + threadIdx.x) >> 5;
    int lane = threadIdx.x & 31;
    if (gw >= TOK) return;

    const float* src;
    if (WIN) {
        src = in + (size_t)unshift_row(gw) * 256;   // gather source == scatter dst map
    } else {
        src = in + (size_t)gw * 256;
    }

    float v[8];
#pragma unroll
    for (int i = 0; i < 8; i++) v[i] = src[lane + 32 * i];

    float s = 0.f;
#pragma unroll
    for (int i = 0; i < 8; i++) s += v[i];
#pragma unroll
    for (int o = 16; o > 0; o >>= 1) s += __shfl_xor_sync(0xffffffffu, s, o);
    float mean = s * (1.0f / 256.0f);

    float q = 0.f;
#pragma unroll
    for (int i = 0; i < 8; i++) { float d = v[i] - mean; q += d * d; }
#pragma unroll
    for (int o = 16; o > 0; o >>= 1) q += __shfl_xor_sync(0xffffffffu, q, o);
    float rstd = rsqrtf(q * (1.0f / 256.0f) + 1e-5f);

    float* orow = out + (size_t)gw * 256;
#pragma unroll
    for (int i = 0; i < 8; i++) {
        int cc = lane + 32 * i;
        orow[cc] = (v[i] - mean) * rstd * gm[cc] + bt[cc];
    }
}

// ---------------- tf32 tensor-core GEMM ----------------
// C[M,NN] = A[M,K] @ B[K,NN] + epilogue
// MODE 0: out = acc + bias                                  (QKV)
// MODE 1: out[dst] = res[dst] + acc + bias, dst = unshift   (proj + scatter + residual)
// MODE 2: out = gelu(acc + bias)                            (FC1)
// MODE 3: out = res + acc + bias                            (FC2 + residual)
//
// block tile 128x128, BK=16, 8 warps (2x4), warp tile 64x32,
// mma m16n8k8 tf32 with fp32 accumulate.
template<int K, int NN, int MODE>
__global__ __launch_bounds__(256) void mma_gemm(
    const float* __restrict__ A, const float* __restrict__ Bm,
    const float* __restrict__ bias, float* out, const float* res)
{
    __shared__ __align__(16) uint32_t As[2][128][20];   // [buf][m][k], stride 20 for ldsm
    __shared__ __align__(16) uint32_t Bs[2][16][132];   // [buf][k][n], stride 132

    const int tid  = threadIdx.x;
    const int lane = tid & 31;
    const int warp = tid >> 5;
    const int wm   = warp >> 2;   // 0..1  (m band of 64)
    const int wn   = warp & 3;    // 0..3  (n band of 32)
    const int bm = blockIdx.y, bn = blockIdx.x;

    // staging: A rows tid/4 and tid/4+64, k-float4 at (tid&3)*4
    const int ar = tid >> 2;
    const int ac = (tid & 3) * 4;
    // staging: B rows tid/32 and tid/32+8, n-float4 at (tid&31)*4
    const int br = tid >> 5;
    const int bc = (tid & 31) * 4;

    const float* Ap = A + (size_t)(bm * 128 + ar) * K + ac;
    const float* Bp = Bm + (size_t)br * NN + bn * 128 + bc;

    float c[4][4][4];
#pragma unroll
    for (int i = 0; i < 4; i++)
#pragma unroll
        for (int j = 0; j < 4; j++)
#pragma unroll
            for (int l = 0; l < 4; l++) c[i][j][l] = 0.f;

    float4 a0 = *(const float4*)Ap;
    float4 a1 = *(const float4*)(Ap + (size_t)64 * K);
    float4 b0 = *(const float4*)Bp;
    float4 b1 = *(const float4*)(Bp + (size_t)8 * NN);

#define STAGE(BUF)                                                              \
    do {                                                                        \
        As[BUF][ar][ac + 0] = f2tf32(a0.x); As[BUF][ar][ac + 1] = f2tf32(a0.y); \
        As[BUF][ar][ac + 2] = f2tf32(a0.z); As[BUF][ar][ac + 3] = f2tf32(a0.w); \
        As[BUF][ar + 64][ac + 0] = f2tf32(a1.x);                                \
        As[BUF][ar + 64][ac + 1] = f2tf32(a1.y);                                \
        As[BUF][ar + 64][ac + 2] = f2tf32(a1.z);                                \
        As[BUF][ar + 64][ac + 3] = f2tf32(a1.w);                                \
        Bs[BUF][br][bc + 0] = f2tf32(b0.x); Bs[BUF][br][bc + 1] = f2tf32(b0.y); \
        Bs[BUF][br][bc + 2] = f2tf32(b0.z); Bs[BUF][br][bc + 3] = f2tf32(b0.w); \
        Bs[BUF][br + 8][bc + 0] = f2tf32(b1.x);                                 \
        Bs[BUF][br + 8][bc + 1] = f2tf32(b1.y);                                 \
        Bs[BUF][br + 8][bc + 2] = f2tf32(b1.z);                                 \
        Bs[BUF][br + 8][bc + 3] = f2tf32(b1.w);                                 \
    } while (0)

    STAGE(0);
    __syncthreads();

    int buf = 0;
    const int KT = K / 16;
    for (int kt = 0; kt < KT; kt++) {
        const bool more = (kt + 1 < KT);
        if (more) {
            a0 = *(const float4*)(Ap + 16);
            a1 = *(const float4*)(Ap + 16 + (size_t)64 * K);
            b0 = *(const float4*)(Bp + (size_t)16 * NN);
            b1 = *(const float4*)(Bp + (size_t)24 * NN);
            Ap += 16; Bp += (size_t)16 * NN;
        }

#pragma unroll
        for (int ks = 0; ks < 2; ks++) {
            // A fragments via ldmatrix.x4 (16x8 tf32 per mi)
            uint32_t af[4][4];
#pragma unroll
            for (int mi = 0; mi < 4; mi++) {
                uint32_t saddr = (uint32_t)__cvta_generic_to_shared(
                    &As[buf][wm * 64 + mi * 16 + (lane & 15)][ks * 8 + (lane >> 4) * 4]);
                asm volatile(
                    "ldmatrix.sync.aligned.m8n8.x4.shared.b16 {%0,%1,%2,%3}, [%4];"
                    : "=r"(af[mi][0]), "=r"(af[mi][1]), "=r"(af[mi][2]), "=r"(af[mi][3])
                    : "r"(saddr));
            }
            // B fragments via scalar LDS (8x8: thread -> (k=lane&3 [+4], n=lane>>2))
            uint32_t bf[4][2];
#pragma unroll
            for (int ni = 0; ni < 4; ni++) {
                int nn = wn * 32 + ni * 8 + (lane >> 2);
                bf[ni][0] = Bs[buf][ks * 8 + (lane & 3)][nn];
                bf[ni][1] = Bs[buf][ks * 8 + 4 + (lane & 3)][nn];
            }
#pragma unroll
            for (int mi = 0; mi < 4; mi++)
#pragma unroll
                for (int ni = 0; ni < 4; ni++) {
                    asm volatile(
                        "mma.sync.aligned.m16n8k8.row.col.f32.tf32.tf32.f32 "
                        "{%0,%1,%2,%3}, {%4,%5,%6,%7}, {%8,%9}, {%0,%1,%2,%3};"
                        : "+f"(c[mi][ni][0]), "+f"(c[mi][ni][1]),
                          "+f"(c[mi][ni][2]), "+f"(c[mi][ni][3])
                        : "r"(af[mi][0]), "r"(af[mi][1]), "r"(af[mi][2]), "r"(af[mi][3]),
                          "r"(bf[ni][0]), "r"(bf[ni][1]));
                }
        }

        if (more) {
            buf ^= 1;
            STAGE(buf);
            __syncthreads();
        }
    }
#undef STAGE

    // ---- epilogue ----
    // C fragment: thread holds rows (lane>>2, lane>>2+8), cols 2*(lane&3), +1
#pragma unroll
    for (int mi = 0; mi < 4; mi++) {
        int mr0 = bm * 128 + wm * 64 + mi * 16 + (lane >> 2);
        int mr1 = mr0 + 8;
        size_t dst0, dst1;
        if (MODE == 1) {
            dst0 = (size_t)unshift_row(mr0);
            dst1 = (size_t)unshift_row(mr1);
        } else {
            dst0 = (size_t)mr0;
            dst1 = (size_t)mr1;
        }
#pragma unroll
        for (int ni = 0; ni < 4; ni++) {
            int col = bn * 128 + wn * 32 + ni * 8 + 2 * (lane & 3);
            float2 bb = *(const float2*)&bias[col];
            float2 o0, o1;
            o0.x = c[mi][ni][0] + bb.x; o0.y = c[mi][ni][1] + bb.y;
            o1.x = c[mi][ni][2] + bb.x; o1.y = c[mi][ni][3] + bb.y;
            if (MODE == 1 || MODE == 3) {
                float2 r0v = *(const float2*)&res[dst0 * NN + col];
                float2 r1v = *(const float2*)&res[dst1 * NN + col];
                o0.x += r0v.x; o0.y += r0v.y;
                o1.x += r1v.x; o1.y += r1v.y;
            }
            if (MODE == 2) {
                o0.x = gelu_exact(o0.x); o0.y = gelu_exact(o0.y);
                o1.x = gelu_exact(o1.x); o1.y = gelu_exact(o1.y);
            }
            *(float2*)&out[dst0 * NN + col] = o0;
            *(float2*)&out[dst1 * NN + col] = o1;
        }
    }
}

// ---------------- windowed attention (one block per window-head) ----------------
__global__ __launch_bounds__(256) void attn_kernel(const float* __restrict__ qkv,
                                                   const float* __restrict__ rpb,
                                                   float* __restrict__ out)
{
    const int wb = blockIdx.x;   // 0..2047
    const int h  = blockIdx.y;   // 0..7
    const int tid = threadIdx.x;

    __shared__ float qs[49 * 33];
    __shared__ float ks[49 * 33];
    __shared__ float vs[49 * 33];
    __shared__ float sc[49 * 49];
    __shared__ float rpb_s[169];
    __shared__ int   lab[49];

    for (int idx = tid; idx < 49 * 32; idx += 256) {
        int n = idx >> 5, d = idx & 31;
        size_t base = (size_t)(wb * 49 + n) * 768 + h * 32 + d;
        qs[n * 33 + d] = qkv[base] * SCALE;
        ks[n * 33 + d] = qkv[base + 256];
        vs[n * 33 + d] = qkv[base + 512];
    }
    for (int i = tid; i < 169; i += 256) rpb_s[i] = rpb[i * 8 + h];
    if (tid < 49) {
        int wwi = wb & 7, wh = (wb >> 3) & 7;
        int r = tid / 7, c = tid % 7;
        int gr = wh * 7 + r, gc = wwi * 7 + c;
        int lr = gr < 49 ? 0 : (gr < 53 ? 1 : 2);
        int lc = gc < 49 ? 0 : (gc < 53 ? 1 : 2);
        lab[tid] = lr * 3 + lc;
    }
    __syncthreads();

    for (int idx = tid; idx < 49 * 49; idx += 256) {
        int i = idx / 49, j = idx % 49;
        float s = 0.f;
#pragma unroll
        for (int d = 0; d < 32; d++) s += qs[i * 33 + d] * ks[j * 33 + d];
        int ri = i / 7, ci = i % 7, rj = j / 7, cj = j % 7;
        s += rpb_s[(ri - rj + 6) * 13 + (ci - cj + 6)];
        if (lab[i] != lab[j]) s -= 100.0f;
        sc[idx] = s;
    }
    __syncthreads();

    if (tid < 49) {
        float mx = -1e30f;
#pragma unroll 7
        for (int j = 0; j < 49; j++) mx = fmaxf(mx, sc[tid * 49 + j]);
        float sum = 0.f;
#pragma unroll 7
        for (int j = 0; j < 49; j++) {
            float e = __expf(sc[tid * 49 + j] - mx);
            sc[tid * 49 + j] = e;
            sum += e;
        }
        float inv = 1.0f / sum;
#pragma unroll 7
        for (int j = 0; j < 49; j++) sc[tid * 49 + j] *= inv;
    }
    __syncthreads();

    for (int idx = tid; idx < 49 * 32; idx += 256) {
        int i = idx >> 5, d = idx & 31;
        float o = 0.f;
#pragma unroll 7
        for (int j = 0; j < 49; j++) o += sc[i * 49 + j] * vs[j * 33 + d];
        out[(size_t)(wb * 49 + i) * 256 + h * 32 + d] = o;
    }
}

// ---------------- launch ----------------
extern "C" void kernel_launch(void* const* d_in, const int* in_sizes, int n_in,
                              void* d_out, int out_size)
{
    const float* x      = (const float*)d_in[0];
    const float* gamma1 = (const float*)d_in[1];
    const float* beta1  = (const float*)d_in[2];
    const float* qkv_w  = (const float*)d_in[3];
    const float* qkv_b  = (const float*)d_in[4];
    const float* proj_w = (const float*)d_in[5];
    const float* proj_b = (const float*)d_in[6];
    const float* rpb    = (const float*)d_in[7];
    const float* gamma2 = (const float*)d_in[8];
    const float* beta2  = (const float*)d_in[9];
    const float* fc1_w  = (const float*)d_in[10];
    const float* fc1_b  = (const float*)d_in[11];
    const float* fc2_w  = (const float*)d_in[12];
    const float* fc2_b  = (const float*)d_in[13];
    float* out = (float*)d_out;

    float *pa, *pqkv, *ph;
    cudaGetSymbolAddress((void**)&pa, g_a);
    cudaGetSymbolAddress((void**)&pqkv, g_qkv);
    cudaGetSymbolAddress((void**)&ph, g_h);

    // 1. LN1 + cyclic shift + window partition -> g_a [TOK, 256]
    ln_kernel<true><<<TOK / 8, 256>>>(x, gamma1, beta1, pa);
    // 2. QKV GEMM -> g_qkv [TOK, 768]
    mma_gemm<256, 768, 0><<<dim3(6, 784), 256>>>(pa, qkv_w, qkv_b, pqkv, nullptr);
    // 3. attention -> g_a (reused) [TOK, 256]
    attn_kernel<<<dim3(2048, 8), 256>>>(pqkv, rpb, pa);
    // 4. proj GEMM + window reverse + unroll-shift scatter + residual -> d_out (= x1)
    mma_gemm<256, 256, 1><<<dim3(2, 784), 256>>>(pa, proj_w, proj_b, out, x);
    // 5. LN2 -> g_qkv (reused as [TOK, 256])
    ln_kernel<false><<<TOK / 8, 256>>>(out, gamma2, beta2, pqkv);
    // 6. FC1 + GELU -> g_h [TOK, 1024]
    mma_gemm<256, 1024, 2><<<dim3(8, 784), 256>>>(pqkv, fc1_w, fc1_b, ph, nullptr);
    // 7. FC2 + residual -> d_out
    mma_gemm<1024, 256, 3><<<dim3(2, 784), 256>>>(ph, fc2_w, fc2_b, out, out);
    (void)in_sizes; (void)n_in; (void)out_size;
}

// round 4
// speedup vs baseline: 1.9629x; 1.0800x over previous
#include <cuda_runtime.h>
#include <math.h>
#include <stdint.h>

// ---------------- static config ----------------
#define TOK   100352          // 32 * 56 * 56 tokens
#define NWIN  2048
#define SCALE 0.17677669529663687f   // 32^-0.5

// ---------------- scratch (device globals; no allocs allowed) ----------------
__device__ float g_a[TOK * 256];      // LN1-window output; reused for attention output
__device__ float g_qkv[TOK * 768];    // QKV; first TOK*256 reused for LN2 output
__device__ float g_h[TOK * 1024];     // FC1/GELU output
// transposed + tf32-rounded weights: qkvT[768][256], projT[256][256], fc1T[1024][256], fc2T[256][1024]
__device__ float g_wT[196608 + 65536 + 262144 + 262144];
#define OFF_QKVT 0
#define OFF_PROJT 196608
#define OFF_FC1T 262144
#define OFF_FC2T 524288

// ---------------- helpers ----------------
__device__ __forceinline__ float tf32r(float x)
{
    uint32_t u;
    asm("cvt.rna.tf32.f32 %0, %1;" : "=r"(u) : "f"(x));
    return __uint_as_float(u);
}

__device__ __forceinline__ float gelu_exact(float x)
{
    return 0.5f * x * (1.0f + erff(x * 0.70710678118654752f));
}

// unshifted destination row for window-layout row mr (window reverse + roll)
__device__ __forceinline__ int unshift_row(int mr)
{
    int ntok = mr % 49; int wb = mr / 49;
    int wwi = wb & 7, wh = (wb >> 3) & 7, b = wb >> 6;
    int r = ntok / 7, c = ntok % 7;
    int oh = wh * 7 + r + 3; if (oh >= 56) oh -= 56;
    int ow = wwi * 7 + c + 3; if (ow >= 56) ow -= 56;
    return b * 3136 + oh * 56 + ow;
}

__device__ __forceinline__ void ldsm4(uint32_t addr, uint32_t& r0, uint32_t& r1,
                                      uint32_t& r2, uint32_t& r3)
{
    asm volatile("ldmatrix.sync.aligned.m8n8.x4.shared.b16 {%0,%1,%2,%3}, [%4];"
                 : "=r"(r0), "=r"(r1), "=r"(r2), "=r"(r3) : "r"(addr));
}

__device__ __forceinline__ void cpa16(uint32_t dst, const void* src)
{
    asm volatile("cp.async.cg.shared.global [%0], [%1], 16;" :: "r"(dst), "l"(src));
}

// ---------------- weight transpose + tf32 round: in[K][N] -> out[N][K] ----------------
__global__ void transpose_tf32(const float* __restrict__ in, float* __restrict__ out,
                               int K, int N)
{
    __shared__ float t[32][33];
    int bx = blockIdx.x * 32;   // n
    int by = blockIdx.y * 32;   // k
    int tx = threadIdx.x, ty = threadIdx.y;
#pragma unroll
    for (int i = 0; i < 32; i += 8)
        t[ty + i][tx] = in[(size_t)(by + ty + i) * N + bx + tx];
    __syncthreads();
#pragma unroll
    for (int i = 0; i < 32; i += 8)
        out[(size_t)(bx + ty + i) * K + by + tx] = tf32r(t[tx][ty + i]);
}

// ---------------- LayerNorm (optionally fused with shift+window gather) ----------------
// output is tf32-rounded (it only feeds tf32 GEMMs)
template<bool WIN>
__global__ void ln_kernel(const float* __restrict__ in, const float* __restrict__ gm,
                          const float* __restrict__ bt, float* __restrict__ out)
{
    int gw   = (blockIdx.x * blockDim.x + threadIdx.x) >> 5;
    int lane = threadIdx.x & 31;
    if (gw >= TOK) return;

    const float* src;
    if (WIN) src = in + (size_t)unshift_row(gw) * 256;
    else     src = in + (size_t)gw * 256;

    float v[8];
#pragma unroll
    for (int i = 0; i < 8; i++) v[i] = src[lane + 32 * i];

    float s = 0.f;
#pragma unroll
    for (int i = 0; i < 8; i++) s += v[i];
#pragma unroll
    for (int o = 16; o > 0; o >>= 1) s += __shfl_xor_sync(0xffffffffu, s, o);
    float mean = s * (1.0f / 256.0f);

    float q = 0.f;
#pragma unroll
    for (int i = 0; i < 8; i++) { float d = v[i] - mean; q += d * d; }
#pragma unroll
    for (int o = 16; o > 0; o >>= 1) q += __shfl_xor_sync(0xffffffffu, q, o);
    float rstd = rsqrtf(q * (1.0f / 256.0f) + 1e-5f);

    float* orow = out + (size_t)gw * 256;
#pragma unroll
    for (int i = 0; i < 8; i++) {
        int cc = lane + 32 * i;
        orow[cc] = tf32r((v[i] - mean) * rstd * gm[cc] + bt[cc]);
    }
}

// ---------------- tf32 tensor-core GEMM ----------------
// C[M,NN] = A[M,K] @ BT^T + epilogue     (BT is [NN][K], tf32-rounded)
// MODE 0: out = acc + bias                                  (QKV)
// MODE 1: out[dst] = res[dst] + acc + bias, dst = unshift   (proj + scatter + residual)
// MODE 2: out = tf32r(gelu(acc + bias))                     (FC1)
// MODE 3: out = res + acc + bias                            (FC2 + residual)
//
// block 128x128, BK=32, 4 warps (2x2), warp tile 64x64, mma m16n8k8 tf32.
// smem: A/B tiles [128 rows][32 floats] = 128B rows, swizzle: granule g at
// phys (g ^ (row&7)), double buffered. cp.async staging, ldmatrix.x4 fragments.
template<int K, int NN, int MODE>
__global__ __launch_bounds__(128) void mma_gemm(
    const float* __restrict__ A, const float* __restrict__ BT,
    const float* __restrict__ bias, float* __restrict__ out,
    const float* __restrict__ res)
{
    extern __shared__ float smdyn[];
    const int tid  = threadIdx.x;
    const int lane = tid & 31;
    const int warp = tid >> 5;
    const int wm = warp >> 1, wn = warp & 1;
    const int bm = blockIdx.y, bn = blockIdx.x;

    const uint32_t sbase = (uint32_t)__cvta_generic_to_shared(smdyn);
    const uint32_t sA0 = sbase;            // 2 buffers x 16KB
    const uint32_t sB0 = sbase + 32768;    // 2 buffers x 16KB

    // staging thread mapping: 16 rows x 8 granules, 8 row-steps of 16
    const int lr = tid >> 3;   // 0..15
    const int lg = tid & 7;    // 0..7
    const uint32_t swz = (uint32_t)((lg ^ (lr & 7)) << 4);
    const float* Ag = A  + (size_t)(bm * 128 + lr) * K + lg * 4;
    const float* Bg = BT + (size_t)(bn * 128 + lr) * K + lg * 4;
    const uint32_t dA = sA0 + lr * 128 + swz;
    const uint32_t dB = sB0 + lr * 128 + swz;

    float c[4][8][4];
#pragma unroll
    for (int i = 0; i < 4; i++)
#pragma unroll
        for (int j = 0; j < 8; j++)
#pragma unroll
            for (int l = 0; l < 4; l++) c[i][j][l] = 0.f;

#define PREF(KT, BUF)                                                     \
    do {                                                                  \
        const float* _a = Ag + (KT) * 32;                                 \
        const float* _b = Bg + (KT) * 32;                                 \
        uint32_t _o = (BUF) * 16384;                                      \
        _Pragma("unroll")                                                 \
        for (int i = 0; i < 8; i++) {                                     \
            cpa16(dA + _o + i * 2048, _a + (size_t)i * 16 * K);           \
            cpa16(dB + _o + i * 2048, _b + (size_t)i * 16 * K);           \
        }                                                                 \
        asm volatile("cp.async.commit_group;");                           \
    } while (0)

    PREF(0, 0);
    asm volatile("cp.async.wait_group 0;");
    __syncthreads();

    // ldmatrix row bases (row&7 == lane&7 for all fragment rows)
    const int l15 = lane & 15, hi = lane >> 4, l7 = lane & 7;
    uint32_t aRow[4], bRow[4];
#pragma unroll
    for (int mi = 0; mi < 4; mi++) aRow[mi] = sA0 + (wm * 64 + mi * 16 + l15) * 128;
#pragma unroll
    for (int j = 0; j < 4; j++)    bRow[j]  = sB0 + (wn * 64 + j * 16 + l15) * 128;

    int buf = 0;
    const int KT = K / 32;
    for (int kt = 0; kt < KT; kt++) {
        if (kt + 1 < KT) PREF(kt + 1, buf ^ 1);
        const uint32_t boff = buf * 16384;
#pragma unroll
        for (int ks = 0; ks < 4; ks++) {
            const uint32_t gph = (uint32_t)(((2 * ks + hi) ^ l7) << 4) + boff;
            uint32_t af[4][4], bq[4][4];
#pragma unroll
            for (int mi = 0; mi < 4; mi++)
                ldsm4(aRow[mi] + gph, af[mi][0], af[mi][1], af[mi][2], af[mi][3]);
#pragma unroll
            for (int j = 0; j < 4; j++)
                ldsm4(bRow[j] + gph, bq[j][0], bq[j][1], bq[j][2], bq[j][3]);
#pragma unroll
            for (int mi = 0; mi < 4; mi++)
#pragma unroll
                for (int ni = 0; ni < 8; ni++) {
                    asm volatile(
                        "mma.sync.aligned.m16n8k8.row.col.f32.tf32.tf32.f32 "
                        "{%0,%1,%2,%3}, {%4,%5,%6,%7}, {%8,%9}, {%0,%1,%2,%3};"
                        : "+f"(c[mi][ni][0]), "+f"(c[mi][ni][1]),
                          "+f"(c[mi][ni][2]), "+f"(c[mi][ni][3])
                        : "r"(af[mi][0]), "r"(af[mi][1]),
                          "r"(af[mi][2]), "r"(af[mi][3]),
                          "r"(bq[ni >> 1][ni & 1]), "r"(bq[ni >> 1][2 + (ni & 1)]));
                }
        }
        if (kt + 1 < KT) {
            asm volatile("cp.async.wait_group 0;");
            __syncthreads();
            buf ^= 1;
        }
    }
#undef PREF

    // ---- epilogue ----
#pragma unroll
    for (int mi = 0; mi < 4; mi++) {
        int mr0 = bm * 128 + wm * 64 + mi * 16 + (lane >> 2);
        int mr1 = mr0 + 8;
        size_t dst0, dst1;
        if (MODE == 1) { dst0 = (size_t)unshift_row(mr0); dst1 = (size_t)unshift_row(mr1); }
        else           { dst0 = (size_t)mr0;              dst1 = (size_t)mr1; }
#pragma unroll
        for (int ni = 0; ni < 8; ni++) {
            int col = bn * 128 + wn * 64 + ni * 8 + 2 * (lane & 3);
            float2 bb = *(const float2*)&bias[col];
            float2 o0, o1;
            o0.x = c[mi][ni][0] + bb.x; o0.y = c[mi][ni][1] + bb.y;
            o1.x = c[mi][ni][2] + bb.x; o1.y = c[mi][ni][3] + bb.y;
            if (MODE == 1 || MODE == 3) {
                float2 r0v = *(const float2*)&res[dst0 * NN + col];
                float2 r1v = *(const float2*)&res[dst1 * NN + col];
                o0.x += r0v.x; o0.y += r0v.y;
                o1.x += r1v.x; o1.y += r1v.y;
            }
            if (MODE == 2) {
                o0.x = tf32r(gelu_exact(o0.x)); o0.y = tf32r(gelu_exact(o0.y));
                o1.x = tf32r(gelu_exact(o1.x)); o1.y = tf32r(gelu_exact(o1.y));
            }
            *(float2*)&out[dst0 * NN + col] = o0;
            *(float2*)&out[dst1 * NN + col] = o1;
        }
    }
}

// ---------------- windowed attention (one block per window-head) ----------------
__global__ __launch_bounds__(256) void attn_kernel(const float* __restrict__ qkv,
                                                   const float* __restrict__ rpb,
                                                   float* __restrict__ out)
{
    const int wb = blockIdx.x;
    const int h  = blockIdx.y;
    const int tid = threadIdx.x;

    __shared__ float qs[49 * 33];
    __shared__ float ks[49 * 33];
    __shared__ float vs[49 * 33];
    __shared__ float sc[49 * 49];
    __shared__ float rpb_s[169];
    __shared__ int   lab[49];

    for (int idx = tid; idx < 49 * 32; idx += 256) {
        int n = idx >> 5, d = idx & 31;
        size_t base = (size_t)(wb * 49 + n) * 768 + h * 32 + d;
        qs[n * 33 + d] = qkv[base] * SCALE;
        ks[n * 33 + d] = qkv[base + 256];
        vs[n * 33 + d] = qkv[base + 512];
    }
    for (int i = tid; i < 169; i += 256) rpb_s[i] = rpb[i * 8 + h];
    if (tid < 49) {
        int wwi = wb & 7, wh = (wb >> 3) & 7;
        int r = tid / 7, c = tid % 7;
        int gr = wh * 7 + r, gc = wwi * 7 + c;
        int lr = gr < 49 ? 0 : (gr < 53 ? 1 : 2);
        int lc = gc < 49 ? 0 : (gc < 53 ? 1 : 2);
        lab[tid] = lr * 3 + lc;
    }
    __syncthreads();

    for (int idx = tid; idx < 49 * 49; idx += 256) {
        int i = idx / 49, j = idx % 49;
        float s = 0.f;
#pragma unroll
        for (int d = 0; d < 32; d++) s += qs[i * 33 + d] * ks[j * 33 + d];
        int ri = i / 7, ci = i % 7, rj = j / 7, cj = j % 7;
        s += rpb_s[(ri - rj + 6) * 13 + (ci - cj + 6)];
        if (lab[i] != lab[j]) s -= 100.0f;
        sc[idx] = s;
    }
    __syncthreads();

    if (tid < 49) {
        float mx = -1e30f;
#pragma unroll 7
        for (int j = 0; j < 49; j++) mx = fmaxf(mx, sc[tid * 49 + j]);
        float sum = 0.f;
#pragma unroll 7
        for (int j = 0; j < 49; j++) {
            float e = __expf(sc[tid * 49 + j] - mx);
            sc[tid * 49 + j] = e;
            sum += e;
        }
        float inv = 1.0f / sum;
#pragma unroll 7
        for (int j = 0; j < 49; j++) sc[tid * 49 + j] *= inv;
    }
    __syncthreads();

    for (int idx = tid; idx < 49 * 32; idx += 256) {
        int i = idx >> 5, d = idx & 31;
        float o = 0.f;
#pragma unroll 7
        for (int j = 0; j < 49; j++) o += sc[i * 49 + j] * vs[j * 33 + d];
        out[(size_t)(wb * 49 + i) * 256 + h * 32 + d] = tf32r(o);  // feeds proj GEMM
    }
}

// ---------------- launch ----------------
extern "C" void kernel_launch(void* const* d_in, const int* in_sizes, int n_in,
                              void* d_out, int out_size)
{
    const float* x      = (const float*)d_in[0];
    const float* gamma1 = (const float*)d_in[1];
    const float* beta1  = (const float*)d_in[2];
    const float* qkv_w  = (const float*)d_in[3];
    const float* qkv_b  = (const float*)d_in[4];
    const float* proj_w = (const float*)d_in[5];
    const float* proj_b = (const float*)d_in[6];
    const float* rpb    = (const float*)d_in[7];
    const float* gamma2 = (const float*)d_in[8];
    const float* beta2  = (const float*)d_in[9];
    const float* fc1_w  = (const float*)d_in[10];
    const float* fc1_b  = (const float*)d_in[11];
    const float* fc2_w  = (const float*)d_in[12];
    const float* fc2_b  = (const float*)d_in[13];
    float* out = (float*)d_out;

    float *pa, *pqkv, *ph, *pw;
    cudaGetSymbolAddress((void**)&pa, g_a);
    cudaGetSymbolAddress((void**)&pqkv, g_qkv);
    cudaGetSymbolAddress((void**)&ph, g_h);
    cudaGetSymbolAddress((void**)&pw, g_wT);

    const int SMEM = 65536;
    cudaFuncSetAttribute(mma_gemm<256, 768, 0>, cudaFuncAttributeMaxDynamicSharedMemorySize, SMEM);
    cudaFuncSetAttribute(mma_gemm<256, 256, 1>, cudaFuncAttributeMaxDynamicSharedMemorySize, SMEM);
    cudaFuncSetAttribute(mma_gemm<256, 1024, 2>, cudaFuncAttributeMaxDynamicSharedMemorySize, SMEM);
    cudaFuncSetAttribute(mma_gemm<1024, 256, 3>, cudaFuncAttributeMaxDynamicSharedMemorySize, SMEM);

    // 0. transpose + tf32-round weights
    transpose_tf32<<<dim3(768 / 32, 256 / 32), dim3(32, 8)>>>(qkv_w, pw + OFF_QKVT, 256, 768);
    transpose_tf32<<<dim3(256 / 32, 256 / 32), dim3(32, 8)>>>(proj_w, pw + OFF_PROJT, 256, 256);
    transpose_tf32<<<dim3(1024 / 32, 256 / 32), dim3(32, 8)>>>(fc1_w, pw + OFF_FC1T, 256, 1024);
    transpose_tf32<<<dim3(256 / 32, 1024 / 32), dim3(32, 8)>>>(fc2_w, pw + OFF_FC2T, 1024, 256);

    // 1. LN1 + cyclic shift + window partition -> g_a
    ln_kernel<true><<<TOK / 8, 256>>>(x, gamma1, beta1, pa);
    // 2. QKV GEMM -> g_qkv
    mma_gemm<256, 768, 0><<<dim3(6, 784), 128, SMEM>>>(pa, pw + OFF_QKVT, qkv_b, pqkv, nullptr);
    // 3. attention -> g_a (reused)
    attn_kernel<<<dim3(2048, 8), 256>>>(pqkv, rpb, pa);
    // 4. proj GEMM + window reverse + roll scatter + residual -> d_out
    mma_gemm<256, 256, 1><<<dim3(2, 784), 128, SMEM>>>(pa, pw + OFF_PROJT, proj_b, out, x);
    // 5. LN2 -> g_qkv (reused)
    ln_kernel<false><<<TOK / 8, 256>>>(out, gamma2, beta2, pqkv);
    // 6. FC1 + GELU -> g_h
    mma_gemm<256, 1024, 2><<<dim3(8, 784), 128, SMEM>>>(pqkv, pw + OFF_FC1T, fc1_b, ph, nullptr);
    // 7. FC2 + residual -> d_out
    mma_gemm<1024, 256, 3><<<dim3(2, 784), 128, SMEM>>>(ph, pw + OFF_FC2T, fc2_b, out, out);
    (void)in_sizes; (void)n_in; (void)out_size;
}